// round 1
// baseline (speedup 1.0000x reference)
#include <cuda_runtime.h>
#include <cstdint>

#define BSZ 4096
#define DIM 1024
#define NST 2900000

#define GAMMA_S 0.8f
#define GAMMA_U 0.8f
#define RHO 0.1f
#define EPS_ 1e-10f
#define TAU_MIN_ 0.005f
#define TAU_MAX_ 1.0f
#define GRAD_CLIP_ 5.0f
#define ETA_INIT_ 0.01f
#define ETA_MIN_ 0.0001f

// ----- output layout (flattened reference tuple) -----
#define OG_I   0
#define OG_T   (BSZ)
#define OGR_I  (2*BSZ)
#define OGR_T  (3*BSZ)
#define O_LOSS (4*BSZ)
#define O_AVGI (4*BSZ+1)
#define O_AVGT (4*BSZ+2)
#define O_STATE (4*BSZ+3)
// state order: s_I, s_T, u_I, u_T, b_I, b_T, tau_I, tau_T
#define O_SI   (O_STATE + 0*NST)
#define O_ST   (O_STATE + 1*NST)
#define O_UI   (O_STATE + 2*NST)
#define O_UT   (O_STATE + 3*NST)
#define O_BI   (O_STATE + 4*NST)
#define O_BT   (O_STATE + 5*NST)
#define O_TAUI (O_STATE + 6*NST)
#define O_TAUT (O_STATE + 7*NST)

// ----- scratch -----
__device__ float g_sim[(size_t)BSZ * BSZ];   // 64 MB
__device__ float g_loss_img[BSZ];
__device__ float g_loss_txt[BSZ];

// ===================== GEMM: sim = imf @ txf^T (tf32 mma) =====================

__device__ __forceinline__ uint32_t f2tf32(float x) {
    uint32_t r;
    asm("cvt.rna.tf32.f32 %0, %1;" : "=r"(r) : "f"(x));
    return r;
}

__device__ __forceinline__ void mma_tf32(float* c, uint32_t a0, uint32_t a1,
                                         uint32_t a2, uint32_t a3,
                                         uint32_t b0, uint32_t b1) {
    asm volatile(
        "mma.sync.aligned.m16n8k8.row.col.f32.tf32.tf32.f32 "
        "{%0,%1,%2,%3}, {%4,%5,%6,%7}, {%8,%9}, {%0,%1,%2,%3};"
        : "+f"(c[0]), "+f"(c[1]), "+f"(c[2]), "+f"(c[3])
        : "r"(a0), "r"(a1), "r"(a2), "r"(a3), "r"(b0), "r"(b1));
}

// BM=BN=128, BK=16, 256 threads, warp grid 2(m) x 4(n), warp tile 64x32
__global__ void __launch_bounds__(256) gemm_tf32_kernel(
    const float* __restrict__ A, const float* __restrict__ Bm)
{
    __shared__ uint32_t As[16][132];
    __shared__ uint32_t Bs[16][132];

    const int m0 = blockIdx.y * 128;
    const int n0 = blockIdx.x * 128;
    const int tid = threadIdx.x;
    const int lane = tid & 31, wid = tid >> 5;
    const int wm = (wid & 1) * 64;       // warp m-offset within block
    const int wn = (wid >> 1) * 32;      // warp n-offset within block
    const int g = lane >> 2, t4 = lane & 3;

    float acc[4][4][4];
#pragma unroll
    for (int a = 0; a < 4; a++)
#pragma unroll
        for (int b = 0; b < 4; b++)
#pragma unroll
            for (int r = 0; r < 4; r++) acc[a][b][r] = 0.f;

    for (int k0 = 0; k0 < DIM; k0 += 16) {
#pragma unroll
        for (int it = 0; it < 2; it++) {
            int fid = tid + it * 256;           // 0..511
            int row = fid >> 2;                 // 0..127
            int c4 = fid & 3;                   // float4 index within 16 k's
            float4 va = *(const float4*)(A + (size_t)(m0 + row) * DIM + k0 + c4 * 4);
            float4 vb = *(const float4*)(Bm + (size_t)(n0 + row) * DIM + k0 + c4 * 4);
            As[c4 * 4 + 0][row] = f2tf32(va.x);
            As[c4 * 4 + 1][row] = f2tf32(va.y);
            As[c4 * 4 + 2][row] = f2tf32(va.z);
            As[c4 * 4 + 3][row] = f2tf32(va.w);
            Bs[c4 * 4 + 0][row] = f2tf32(vb.x);
            Bs[c4 * 4 + 1][row] = f2tf32(vb.y);
            Bs[c4 * 4 + 2][row] = f2tf32(vb.z);
            Bs[c4 * 4 + 3][row] = f2tf32(vb.w);
        }
        __syncthreads();

#pragma unroll
        for (int ks = 0; ks < 2; ks++) {
            const int kb = ks * 8;
            uint32_t af[4][4], bf[4][2];
#pragma unroll
            for (int mt = 0; mt < 4; mt++) {
                int mb = wm + mt * 16 + g;
                af[mt][0] = As[kb + t4][mb];
                af[mt][1] = As[kb + t4][mb + 8];
                af[mt][2] = As[kb + t4 + 4][mb];
                af[mt][3] = As[kb + t4 + 4][mb + 8];
            }
#pragma unroll
            for (int nt = 0; nt < 4; nt++) {
                int nb = wn + nt * 8 + g;
                bf[nt][0] = Bs[kb + t4][nb];
                bf[nt][1] = Bs[kb + t4 + 4][nb];
            }
#pragma unroll
            for (int mt = 0; mt < 4; mt++)
#pragma unroll
                for (int nt = 0; nt < 4; nt++)
                    mma_tf32(acc[mt][nt], af[mt][0], af[mt][1], af[mt][2], af[mt][3],
                             bf[nt][0], bf[nt][1]);
        }
        __syncthreads();
    }

#pragma unroll
    for (int mt = 0; mt < 4; mt++) {
#pragma unroll
        for (int nt = 0; nt < 4; nt++) {
            int r0 = m0 + wm + mt * 16 + g;
            int cc = n0 + wn + nt * 8 + t4 * 2;
            *(float2*)(g_sim + (size_t)r0 * BSZ + cc) =
                make_float2(acc[mt][nt][0], acc[mt][nt][1]);
            *(float2*)(g_sim + (size_t)(r0 + 8) * BSZ + cc) =
                make_float2(acc[mt][nt][2], acc[mt][nt][3]);
        }
    }
}

// ===================== helpers =====================

__device__ __forceinline__ float eta_of(int ep, int mep) {
    float r = (float)ep / (float)mep;
    return ETA_MIN_ + (ETA_INIT_ - ETA_MIN_) * cosf(1.5707963267948966f * r);
}

// ===================== row pass (image side) =====================

__global__ void __launch_bounds__(256) row_kernel(
    const float* __restrict__ tau_I, const float* __restrict__ s_I,
    const float* __restrict__ u_I, const float* __restrict__ b_I,
    const int* __restrict__ image_ids, const int* __restrict__ epoch,
    const int* __restrict__ max_epoch, float* __restrict__ out)
{
    __shared__ float srow[BSZ];
    __shared__ float redA[8];
    __shared__ float redB[8];
    __shared__ float sc_bcast;

    const int i = blockIdx.x;
    const int tid = threadIdx.x;
    const float* rowp = g_sim + (size_t)i * BSZ;

    for (int j = tid; j < BSZ; j += 256) srow[j] = rowp[j];
    __syncthreads();

    const float diag = srow[i];
    const int id = image_ids[i];
    const float tau = tau_I[id];

    // ---- max of idt over row ----
    float m = -1e30f;
    for (int j = tid; j < BSZ; j += 256) {
        float x = (srow[j] - diag) / tau;
        m = fmaxf(m, x);
    }
#pragma unroll
    for (int o = 16; o; o >>= 1) m = fmaxf(m, __shfl_xor_sync(0xffffffffu, m, o));
    if ((tid & 31) == 0) redA[tid >> 5] = m;
    __syncthreads();
    if (tid == 0) {
        float v = redA[0];
#pragma unroll
        for (int w = 1; w < 8; w++) v = fmaxf(v, redA[w]);
        float old_b = b_I[id];
        sc_bcast = fmaxf(v, old_b);
    }
    __syncthreads();
    const float new_b = sc_bcast;

    // ---- sums: S = sum exp(idt - b), W = sum exp(idt - b) * idt ----
    float S = 0.f, W = 0.f;
    for (int j = tid; j < BSZ; j += 256) {
        float x = (srow[j] - diag) / tau;
        float e = expf(x - new_b);
        S += e;
        W += e * x;
    }
#pragma unroll
    for (int o = 16; o; o >>= 1) {
        S += __shfl_xor_sync(0xffffffffu, S, o);
        W += __shfl_xor_sync(0xffffffffu, W, o);
    }
    if ((tid & 31) == 0) { redA[tid >> 5] = S; redB[tid >> 5] = W; }
    __syncthreads();

    if (tid == 0) {
        float Ssum = 0.f, Wsum = 0.f;
#pragma unroll
        for (int w = 0; w < 8; w++) { Ssum += redA[w]; Wsum += redB[w]; }
        const float old_b = b_I[id];
        const float gI = Ssum / (float)(BSZ - 1);
        const float s_new = (1.f - GAMMA_S) * s_I[id] * expf(old_b - new_b) + GAMMA_S * gI;
        const float wsum = Wsum / (s_new + EPS_) / (float)(BSZ - 1);
        const float loss = tau * wsum;
        const float grad = logf(s_new) + new_b + RHO - wsum;
        const float gclip = fminf(fmaxf(grad, -GRAD_CLIP_), GRAD_CLIP_);
        const float u_new = (1.f - GAMMA_U) * u_I[id] + GAMMA_U * gclip;
        const float eta = eta_of(*epoch, *max_epoch);
        const float tau_new = fminf(fmaxf(tau - eta * u_new, TAU_MIN_), TAU_MAX_);

        out[OG_I + i] = gI;
        out[OGR_I + i] = grad;
        g_loss_img[i] = loss;
        out[O_SI + id] = s_new;
        out[O_BI + id] = new_b;
        out[O_UI + id] = u_new;
        out[O_TAUI + id] = tau_new;
    }
}

// ===================== column pass (text side, online softmax) =====================

#define CB 32
#define RT 64

__global__ void __launch_bounds__(256) col_kernel(
    const float* __restrict__ tau_T, const float* __restrict__ s_T,
    const float* __restrict__ u_T, const float* __restrict__ b_T,
    const int* __restrict__ text_ids, const int* __restrict__ epoch,
    const int* __restrict__ max_epoch, float* __restrict__ out)
{
    __shared__ float tile[RT][CB + 1];
    __shared__ float dshr[CB], tshr[CB];
    __shared__ float m8[8][CB], S8[8][CB], W8[8][CB];

    const int c0 = blockIdx.x * CB;
    const int tid = threadIdx.x;

    if (tid < CB) {
        int j = c0 + tid;
        dshr[tid] = g_sim[(size_t)j * BSZ + j];
        tshr[tid] = tau_T[text_ids[j]];
    }
    __syncthreads();

    const int col = tid & 31;
    const int rg = tid >> 5;
    const float diag = dshr[col];
    const float tau = tshr[col];

    float m = -1e30f, S = 0.f, W = 0.f;

    for (int r0 = 0; r0 < BSZ; r0 += RT) {
#pragma unroll
        for (int it = 0; it < (RT * CB) / 256; it++) {
            int idx = tid + it * 256;
            int r = idx >> 5, c = idx & 31;
            tile[r][c] = g_sim[(size_t)(r0 + r) * BSZ + c0 + c];
        }
        __syncthreads();
#pragma unroll
        for (int rr = 0; rr < 8; rr++) {
            float x = (tile[rg * 8 + rr][col] - diag) / tau;
            if (x > m) {
                float sc = expf(m - x);
                S *= sc; W *= sc; m = x;
            }
            float e = expf(x - m);
            S += e;
            W += e * x;
        }
        __syncthreads();
    }

    m8[rg][col] = m; S8[rg][col] = S; W8[rg][col] = W;
    __syncthreads();

    if (tid < CB) {
        const int j = c0 + tid;
        const int id = text_ids[j];
        float M = -1e30f;
#pragma unroll
        for (int gq = 0; gq < 8; gq++) M = fmaxf(M, m8[gq][tid]);
        const float old_b = b_T[id];
        const float new_b = fmaxf(M, old_b);
        float Ssum = 0.f, Wsum = 0.f;
#pragma unroll
        for (int gq = 0; gq < 8; gq++) {
            float sc = expf(m8[gq][tid] - new_b);
            Ssum += S8[gq][tid] * sc;
            Wsum += W8[gq][tid] * sc;
        }
        const float gT = Ssum / (float)(BSZ - 1);
        const float s_new = (1.f - GAMMA_S) * s_T[id] * expf(old_b - new_b) + GAMMA_S * gT;
        const float wsum = Wsum / (s_new + EPS_) / (float)(BSZ - 1);
        const float loss = tau * wsum;
        const float grad = logf(s_new) + new_b + RHO - wsum;
        const float gclip = fminf(fmaxf(grad, -GRAD_CLIP_), GRAD_CLIP_);
        const float u_new = (1.f - GAMMA_U) * u_T[id] + GAMMA_U * gclip;
        const float eta = eta_of(*epoch, *max_epoch);
        const float tau_new = fminf(fmaxf(tau - eta * u_new, TAU_MIN_), TAU_MAX_);

        out[OG_T + j] = gT;
        out[OGR_T + j] = grad;
        g_loss_txt[j] = loss;
        out[O_ST + id] = s_new;
        out[O_BT + id] = new_b;
        out[O_UT + id] = u_new;
        out[O_TAUT + id] = tau_new;
    }
}

// ===================== state copy =====================

__global__ void __launch_bounds__(256) copy_state(
    const float* __restrict__ s0, const float* __restrict__ s1,
    const float* __restrict__ s2, const float* __restrict__ s3,
    const float* __restrict__ s4, const float* __restrict__ s5,
    const float* __restrict__ s6, const float* __restrict__ s7,
    float* __restrict__ out)
{
    const float* srcs[8] = {s0, s1, s2, s3, s4, s5, s6, s7};
    int idx4 = blockIdx.x * 256 + threadIdx.x;
    if (idx4 >= NST / 4) return;
    int a = blockIdx.y;
    float4 v = ((const float4*)srcs[a])[idx4];
    float* dst = out + O_STATE + (size_t)a * NST + (size_t)idx4 * 4;
    dst[0] = v.x; dst[1] = v.y; dst[2] = v.z; dst[3] = v.w;
}

// ===================== finalize (deterministic reductions) =====================

__global__ void __launch_bounds__(256) finalize_kernel(
    const float* __restrict__ tau_I, const float* __restrict__ tau_T,
    const int* __restrict__ image_ids, const int* __restrict__ text_ids,
    float* __restrict__ out)
{
    __shared__ float r0[8], r1[8], r2[8], r3[8];
    const int tid = threadIdx.x;
    float sli = 0.f, slt = 0.f, sti = 0.f, stt = 0.f;
    for (int i = tid; i < BSZ; i += 256) {
        sli += g_loss_img[i];
        slt += g_loss_txt[i];
        sti += tau_I[image_ids[i]];
        stt += tau_T[text_ids[i]];
    }
#pragma unroll
    for (int o = 16; o; o >>= 1) {
        sli += __shfl_xor_sync(0xffffffffu, sli, o);
        slt += __shfl_xor_sync(0xffffffffu, slt, o);
        sti += __shfl_xor_sync(0xffffffffu, sti, o);
        stt += __shfl_xor_sync(0xffffffffu, stt, o);
    }
    if ((tid & 31) == 0) {
        r0[tid >> 5] = sli; r1[tid >> 5] = slt;
        r2[tid >> 5] = sti; r3[tid >> 5] = stt;
    }
    __syncthreads();
    if (tid == 0) {
        float a = 0.f, b = 0.f, c = 0.f, d = 0.f;
#pragma unroll
        for (int w = 0; w < 8; w++) { a += r0[w]; b += r1[w]; c += r2[w]; d += r3[w]; }
        out[O_LOSS] = a / (float)BSZ + b / (float)BSZ;
        out[O_AVGI] = c / (float)BSZ;
        out[O_AVGT] = d / (float)BSZ;
    }
}

// ===================== launch =====================

extern "C" void kernel_launch(void* const* d_in, const int* in_sizes, int n_in,
                              void* d_out, int out_size)
{
    const float* imf   = (const float*)d_in[0];
    const float* txf   = (const float*)d_in[1];
    const float* s_I   = (const float*)d_in[2];
    const float* s_T   = (const float*)d_in[3];
    const float* tau_I = (const float*)d_in[4];
    const float* tau_T = (const float*)d_in[5];
    const float* u_I   = (const float*)d_in[6];
    const float* u_T   = (const float*)d_in[7];
    const float* b_I   = (const float*)d_in[8];
    const float* b_T   = (const float*)d_in[9];
    const int* image_ids = (const int*)d_in[10];
    const int* text_ids  = (const int*)d_in[11];
    const int* epoch     = (const int*)d_in[12];
    const int* max_epoch = (const int*)d_in[13];
    float* out = (float*)d_out;

    gemm_tf32_kernel<<<dim3(BSZ / 128, BSZ / 128), 256>>>(imf, txf);
    copy_state<<<dim3((NST / 4 + 255) / 256, 8), 256>>>(
        s_I, s_T, u_I, u_T, b_I, b_T, tau_I, tau_T, out);
    row_kernel<<<BSZ, 256>>>(tau_I, s_I, u_I, b_I, image_ids, epoch, max_epoch, out);
    col_kernel<<<BSZ / CB, 256>>>(tau_T, s_T, u_T, b_T, text_ids, epoch, max_epoch, out);
    finalize_kernel<<<1, 256>>>(tau_I, tau_T, image_ids, text_ids, out);
}

// round 3
// speedup vs baseline: 2.5319x; 2.5319x over previous
#include <cuda_runtime.h>
#include <cstdint>

#define BSZ 4096
#define DIM 1024
#define NST 2900000

#define GAMMA_S 0.8f
#define GAMMA_U 0.8f
#define RHO 0.1f
#define EPS_ 1e-10f
#define TAU_MIN_ 0.005f
#define TAU_MAX_ 1.0f
#define GRAD_CLIP_ 5.0f
#define ETA_INIT_ 0.01f
#define ETA_MIN_ 0.0001f

// ----- output layout (flattened reference tuple) -----
#define OG_I   0
#define OG_T   (BSZ)
#define OGR_I  (2*BSZ)
#define OGR_T  (3*BSZ)
#define O_LOSS (4*BSZ)
#define O_AVGI (4*BSZ+1)
#define O_AVGT (4*BSZ+2)
#define O_STATE (4*BSZ+3)
#define O_SI   (O_STATE + 0*NST)
#define O_ST   (O_STATE + 1*NST)
#define O_UI   (O_STATE + 2*NST)
#define O_UT   (O_STATE + 3*NST)
#define O_BI   (O_STATE + 4*NST)
#define O_BT   (O_STATE + 5*NST)
#define O_TAUI (O_STATE + 6*NST)
#define O_TAUT (O_STATE + 7*NST)

// ----- scratch (tile partials, ~3 MB; no 64 MB sim) -----
__device__ float g_rowM[BSZ * 32], g_rowS[BSZ * 32], g_rowW[BSZ * 32];
__device__ float g_colM[BSZ * 32], g_colS[BSZ * 32], g_colW[BSZ * 32];
__device__ float g_diag[BSZ];
__device__ float g_loss_img[BSZ], g_loss_txt[BSZ];

// ===================== tf32 mma =====================

__device__ __forceinline__ uint32_t f2tf32(float x) {
    uint32_t r;
    asm("cvt.rna.tf32.f32 %0, %1;" : "=r"(r) : "f"(x));
    return r;
}

__device__ __forceinline__ void mma_tf32(float* c, uint32_t a0, uint32_t a1,
                                         uint32_t a2, uint32_t a3,
                                         uint32_t b0, uint32_t b1) {
    asm volatile(
        "mma.sync.aligned.m16n8k8.row.col.f32.tf32.tf32.f32 "
        "{%0,%1,%2,%3}, {%4,%5,%6,%7}, {%8,%9}, {%0,%1,%2,%3};"
        : "+f"(c[0]), "+f"(c[1]), "+f"(c[2]), "+f"(c[3])
        : "r"(a0), "r"(a1), "r"(a2), "r"(a3), "r"(b0), "r"(b1));
}

struct SGemm { float As[2][128][20]; float Bs[2][128][20]; };
struct SEpi {
    float tauR[128], tauT[128];
    float pm[128][4], pS[128][4], pW[128][4];
    float cm[128][2], cS[128][2], cW[128][2];
};
union SU { SGemm g; SEpi e; };

__device__ __forceinline__ void omerge(float& m, float& S, float& W,
                                       float om, float oS, float oW) {
    float mn = fmaxf(m, om);
    float ea = __expf(m - mn), eb = __expf(om - mn);
    S = S * ea + oS * eb;
    W = W * ea + oW * eb;
    m = mn;
}

// ===================== GEMM + fused softmax partials =====================

__global__ void __launch_bounds__(256, 2) gemm_fused(
    const float* __restrict__ A, const float* __restrict__ Bm,
    const float* __restrict__ tau_I, const float* __restrict__ tau_T,
    const int* __restrict__ image_ids, const int* __restrict__ text_ids)
{
    __shared__ __align__(16) SU sm;

    const int tid = threadIdx.x;
    const int lane = tid & 31, wid = tid >> 5;
    const int m0 = blockIdx.y * 128, n0 = blockIdx.x * 128;
    const int wm = (wid & 1) * 64, wn = (wid >> 1) * 32;
    const int g = lane >> 2, t4 = lane & 3;

    float acc[4][4][4];
#pragma unroll
    for (int a = 0; a < 4; a++)
#pragma unroll
        for (int b = 0; b < 4; b++)
#pragma unroll
            for (int r = 0; r < 4; r++) acc[a][b][r] = 0.f;

    // ---- async stage loader: 128x16 floats each of A,B per stage ----
    auto load_stage = [&](int s, int k0) {
#pragma unroll
        for (int it = 0; it < 2; it++) {
            int f = tid + it * 256;
            int r = f >> 2, kq = (f & 3) * 4;
            uint32_t da = (uint32_t)__cvta_generic_to_shared(&sm.g.As[s][r][kq]);
            const float* pa = A + (size_t)(m0 + r) * DIM + k0 + kq;
            asm volatile("cp.async.cg.shared.global [%0], [%1], 16;\n"
                         :: "r"(da), "l"(pa) : "memory");
            uint32_t db = (uint32_t)__cvta_generic_to_shared(&sm.g.Bs[s][r][kq]);
            const float* pb = Bm + (size_t)(n0 + r) * DIM + k0 + kq;
            asm volatile("cp.async.cg.shared.global [%0], [%1], 16;\n"
                         :: "r"(db), "l"(pb) : "memory");
        }
        asm volatile("cp.async.commit_group;\n" ::: "memory");
    };

    auto compute_stage = [&](int s) {
#pragma unroll
        for (int ks = 0; ks < 2; ks++) {
            const int kb = ks * 8;
            uint32_t af[4][4], bf[4][2];
#pragma unroll
            for (int mt = 0; mt < 4; mt++) {
                int mb = wm + mt * 16 + g;
                af[mt][0] = f2tf32(sm.g.As[s][mb][kb + t4]);
                af[mt][1] = f2tf32(sm.g.As[s][mb + 8][kb + t4]);
                af[mt][2] = f2tf32(sm.g.As[s][mb][kb + t4 + 4]);
                af[mt][3] = f2tf32(sm.g.As[s][mb + 8][kb + t4 + 4]);
            }
#pragma unroll
            for (int nt = 0; nt < 4; nt++) {
                int nb = wn + nt * 8 + g;
                bf[nt][0] = f2tf32(sm.g.Bs[s][nb][kb + t4]);
                bf[nt][1] = f2tf32(sm.g.Bs[s][nb][kb + t4 + 4]);
            }
#pragma unroll
            for (int mt = 0; mt < 4; mt++)
#pragma unroll
                for (int nt = 0; nt < 4; nt++)
                    mma_tf32(acc[mt][nt], af[mt][0], af[mt][1], af[mt][2],
                             af[mt][3], bf[nt][0], bf[nt][1]);
        }
    };

    load_stage(0, 0);
#pragma unroll 1
    for (int kt = 0; kt < 63; kt++) {
        load_stage((kt + 1) & 1, (kt + 1) * 16);
        asm volatile("cp.async.wait_group 1;\n" ::: "memory");
        __syncthreads();
        compute_stage(kt & 1);
        __syncthreads();
    }
    asm volatile("cp.async.wait_group 0;\n" ::: "memory");
    __syncthreads();
    compute_stage(1);
    __syncthreads();   // done with SGemm smem — epilogue reuses it

    // ---- diag extraction (diagonal blocks only) ----
    if (blockIdx.x == blockIdx.y) {
#pragma unroll
        for (int mt = 0; mt < 4; mt++)
#pragma unroll
            for (int nt = 0; nt < 4; nt++)
#pragma unroll
                for (int h = 0; h < 2; h++)
#pragma unroll
                    for (int ci = 0; ci < 2; ci++) {
                        int rl = wm + mt * 16 + g + 8 * h;
                        int cl = wn + nt * 8 + t4 * 2 + ci;
                        if (rl == cl) g_diag[m0 + rl] = acc[mt][nt][2 * h + ci];
                    }
    }

    // ---- stage taus ----
    if (tid < 128) sm.e.tauR[tid] = tau_I[image_ids[m0 + tid]];
    else           sm.e.tauT[tid - 128] = tau_T[text_ids[n0 + tid - 128]];
    __syncthreads();

    // ---- row partials: per (mt,h) this thread covers 8 cols of row rl ----
#pragma unroll
    for (int mt = 0; mt < 4; mt++) {
#pragma unroll
        for (int h = 0; h < 2; h++) {
            int rl = wm + mt * 16 + g + 8 * h;
            float inv = 1.0f / sm.e.tauR[rl];
            float y[8];
#pragma unroll
            for (int nt = 0; nt < 4; nt++) {
                y[nt * 2]     = acc[mt][nt][2 * h] * inv;
                y[nt * 2 + 1] = acc[mt][nt][2 * h + 1] * inv;
            }
            float m = y[0];
#pragma unroll
            for (int q = 1; q < 8; q++) m = fmaxf(m, y[q]);
            float S = 0.f, W = 0.f;
#pragma unroll
            for (int q = 0; q < 8; q++) {
                float e = __expf(y[q] - m);
                S += e; W += e * y[q];
            }
#pragma unroll
            for (int o = 1; o <= 2; o <<= 1) {
                float om = __shfl_xor_sync(0xffffffffu, m, o);
                float oS = __shfl_xor_sync(0xffffffffu, S, o);
                float oW = __shfl_xor_sync(0xffffffffu, W, o);
                omerge(m, S, W, om, oS, oW);
            }
            if (t4 == 0) {
                sm.e.pm[rl][wid >> 1] = m;
                sm.e.pS[rl][wid >> 1] = S;
                sm.e.pW[rl][wid >> 1] = W;
            }
        }
    }

    // ---- col partials: per (nt,ci) this thread covers 8 rows of col cl ----
#pragma unroll
    for (int nt = 0; nt < 4; nt++) {
#pragma unroll
        for (int ci = 0; ci < 2; ci++) {
            int cl = wn + nt * 8 + t4 * 2 + ci;
            float inv = 1.0f / sm.e.tauT[cl];
            float y[8];
#pragma unroll
            for (int mt = 0; mt < 4; mt++) {
                y[mt * 2]     = acc[mt][nt][ci] * inv;         // h=0
                y[mt * 2 + 1] = acc[mt][nt][2 + ci] * inv;     // h=1
            }
            float m = y[0];
#pragma unroll
            for (int q = 1; q < 8; q++) m = fmaxf(m, y[q]);
            float S = 0.f, W = 0.f;
#pragma unroll
            for (int q = 0; q < 8; q++) {
                float e = __expf(y[q] - m);
                S += e; W += e * y[q];
            }
#pragma unroll
            for (int o = 4; o <= 16; o <<= 1) {
                float om = __shfl_xor_sync(0xffffffffu, m, o);
                float oS = __shfl_xor_sync(0xffffffffu, S, o);
                float oW = __shfl_xor_sync(0xffffffffu, W, o);
                omerge(m, S, W, om, oS, oW);
            }
            if (g == 0) {
                sm.e.cm[cl][wid & 1] = m;
                sm.e.cS[cl][wid & 1] = S;
                sm.e.cW[cl][wid & 1] = W;
            }
        }
    }
    __syncthreads();

    // ---- per-tile merge + gmem write ----
    if (tid < 128) {
        float m = sm.e.pm[tid][0], S = sm.e.pS[tid][0], W = sm.e.pW[tid][0];
#pragma unroll
        for (int p = 1; p < 4; p++)
            omerge(m, S, W, sm.e.pm[tid][p], sm.e.pS[tid][p], sm.e.pW[tid][p]);
        size_t o = (size_t)(m0 + tid) * 32 + blockIdx.x;
        g_rowM[o] = m; g_rowS[o] = S; g_rowW[o] = W;

        float m2 = sm.e.cm[tid][0], S2 = sm.e.cS[tid][0], W2 = sm.e.cW[tid][0];
        omerge(m2, S2, W2, sm.e.cm[tid][1], sm.e.cS[tid][1], sm.e.cW[tid][1]);
        size_t o2 = (size_t)(n0 + tid) * 32 + blockIdx.y;
        g_colM[o2] = m2; g_colS[o2] = S2; g_colW[o2] = W2;
    }
}

// ===================== helpers =====================

__device__ __forceinline__ float eta_of(int ep, int mep) {
    float r = (float)ep / (float)mep;
    return ETA_MIN_ + (ETA_INIT_ - ETA_MIN_) * cosf(1.5707963267948966f * r);
}

// ===================== merges (warp per row/col) =====================

__global__ void __launch_bounds__(256) row_merge(
    const float* __restrict__ tau_I, const float* __restrict__ s_I,
    const float* __restrict__ u_I, const float* __restrict__ b_I,
    const int* __restrict__ image_ids, const int* __restrict__ epoch,
    const int* __restrict__ max_epoch, float* __restrict__ out)
{
    const int i = blockIdx.x * 8 + (threadIdx.x >> 5);
    const int lane = threadIdx.x & 31;
    float m = g_rowM[i * 32 + lane];
    float S = g_rowS[i * 32 + lane];
    float W = g_rowW[i * 32 + lane];
    float M = m;
#pragma unroll
    for (int o = 16; o; o >>= 1) M = fmaxf(M, __shfl_xor_sync(0xffffffffu, M, o));
    const int id = image_ids[i];
    const float tau = tau_I[id];
    const float d = g_diag[i] / tau;
    const float old_b = b_I[id];
    const float new_b = fmaxf(M - d, old_b);
    float e = __expf(m - d - new_b);
    float Sx = S * e;
    float Wx = (W - d * S) * e;
#pragma unroll
    for (int o = 16; o; o >>= 1) {
        Sx += __shfl_xor_sync(0xffffffffu, Sx, o);
        Wx += __shfl_xor_sync(0xffffffffu, Wx, o);
    }
    if (lane == 0) {
        const float gI = Sx / (float)(BSZ - 1);
        const float s_new = (1.f - GAMMA_S) * s_I[id] * expf(old_b - new_b) + GAMMA_S * gI;
        const float wsum = Wx / (s_new + EPS_) / (float)(BSZ - 1);
        const float loss = tau * wsum;
        const float grad = logf(s_new) + new_b + RHO - wsum;
        const float gclip = fminf(fmaxf(grad, -GRAD_CLIP_), GRAD_CLIP_);
        const float u_new = (1.f - GAMMA_U) * u_I[id] + GAMMA_U * gclip;
        const float eta = eta_of(*epoch, *max_epoch);
        const float tau_new = fminf(fmaxf(tau - eta * u_new, TAU_MIN_), TAU_MAX_);
        out[OG_I + i] = gI;
        out[OGR_I + i] = grad;
        g_loss_img[i] = loss;
        out[O_SI + id] = s_new;
        out[O_BI + id] = new_b;
        out[O_UI + id] = u_new;
        out[O_TAUI + id] = tau_new;
    }
}

__global__ void __launch_bounds__(256) col_merge(
    const float* __restrict__ tau_T, const float* __restrict__ s_T,
    const float* __restrict__ u_T, const float* __restrict__ b_T,
    const int* __restrict__ text_ids, const int* __restrict__ epoch,
    const int* __restrict__ max_epoch, float* __restrict__ out)
{
    const int j = blockIdx.x * 8 + (threadIdx.x >> 5);
    const int lane = threadIdx.x & 31;
    float m = g_colM[j * 32 + lane];
    float S = g_colS[j * 32 + lane];
    float W = g_colW[j * 32 + lane];
    float M = m;
#pragma unroll
    for (int o = 16; o; o >>= 1) M = fmaxf(M, __shfl_xor_sync(0xffffffffu, M, o));
    const int id = text_ids[j];
    const float tau = tau_T[id];
    const float d = g_diag[j] / tau;
    const float old_b = b_T[id];
    const float new_b = fmaxf(M - d, old_b);
    float e = __expf(m - d - new_b);
    float Sx = S * e;
    float Wx = (W - d * S) * e;
#pragma unroll
    for (int o = 16; o; o >>= 1) {
        Sx += __shfl_xor_sync(0xffffffffu, Sx, o);
        Wx += __shfl_xor_sync(0xffffffffu, Wx, o);
    }
    if (lane == 0) {
        const float gT = Sx / (float)(BSZ - 1);
        const float s_new = (1.f - GAMMA_S) * s_T[id] * expf(old_b - new_b) + GAMMA_S * gT;
        const float wsum = Wx / (s_new + EPS_) / (float)(BSZ - 1);
        const float loss = tau * wsum;
        const float grad = logf(s_new) + new_b + RHO - wsum;
        const float gclip = fminf(fmaxf(grad, -GRAD_CLIP_), GRAD_CLIP_);
        const float u_new = (1.f - GAMMA_U) * u_T[id] + GAMMA_U * gclip;
        const float eta = eta_of(*epoch, *max_epoch);
        const float tau_new = fminf(fmaxf(tau - eta * u_new, TAU_MIN_), TAU_MAX_);
        out[OG_T + j] = gT;
        out[OGR_T + j] = grad;
        g_loss_txt[j] = loss;
        out[O_ST + id] = s_new;
        out[O_BT + id] = new_b;
        out[O_UT + id] = u_new;
        out[O_TAUT + id] = tau_new;
    }
}

// ===================== state copy =====================

__global__ void __launch_bounds__(256) copy_state(
    const float* __restrict__ s0, const float* __restrict__ s1,
    const float* __restrict__ s2, const float* __restrict__ s3,
    const float* __restrict__ s4, const float* __restrict__ s5,
    const float* __restrict__ s6, const float* __restrict__ s7,
    float* __restrict__ out)
{
    const float* srcs[8] = {s0, s1, s2, s3, s4, s5, s6, s7};
    int idx4 = blockIdx.x * 256 + threadIdx.x;
    if (idx4 >= NST / 4) return;
    int a = blockIdx.y;
    float4 v = ((const float4*)srcs[a])[idx4];
    float* dst = out + O_STATE + (size_t)a * NST + (size_t)idx4 * 4;
    dst[0] = v.x; dst[1] = v.y; dst[2] = v.z; dst[3] = v.w;
}

// ===================== finalize =====================

__global__ void __launch_bounds__(256) finalize_kernel(
    const float* __restrict__ tau_I, const float* __restrict__ tau_T,
    const int* __restrict__ image_ids, const int* __restrict__ text_ids,
    float* __restrict__ out)
{
    __shared__ float r0[8], r1[8], r2[8], r3[8];
    const int tid = threadIdx.x;
    float sli = 0.f, slt = 0.f, sti = 0.f, stt = 0.f;
    for (int i = tid; i < BSZ; i += 256) {
        sli += g_loss_img[i];
        slt += g_loss_txt[i];
        sti += tau_I[image_ids[i]];
        stt += tau_T[text_ids[i]];
    }
#pragma unroll
    for (int o = 16; o; o >>= 1) {
        sli += __shfl_xor_sync(0xffffffffu, sli, o);
        slt += __shfl_xor_sync(0xffffffffu, slt, o);
        sti += __shfl_xor_sync(0xffffffffu, sti, o);
        stt += __shfl_xor_sync(0xffffffffu, stt, o);
    }
    if ((tid & 31) == 0) {
        r0[tid >> 5] = sli; r1[tid >> 5] = slt;
        r2[tid >> 5] = sti; r3[tid >> 5] = stt;
    }
    __syncthreads();
    if (tid == 0) {
        float a = 0.f, b = 0.f, c = 0.f, d = 0.f;
#pragma unroll
        for (int w = 0; w < 8; w++) { a += r0[w]; b += r1[w]; c += r2[w]; d += r3[w]; }
        out[O_LOSS] = a / (float)BSZ + b / (float)BSZ;
        out[O_AVGI] = c / (float)BSZ;
        out[O_AVGT] = d / (float)BSZ;
    }
}

// ===================== launch =====================

extern "C" void kernel_launch(void* const* d_in, const int* in_sizes, int n_in,
                              void* d_out, int out_size)
{
    const float* imf   = (const float*)d_in[0];
    const float* txf   = (const float*)d_in[1];
    const float* s_I   = (const float*)d_in[2];
    const float* s_T   = (const float*)d_in[3];
    const float* tau_I = (const float*)d_in[4];
    const float* tau_T = (const float*)d_in[5];
    const float* u_I   = (const float*)d_in[6];
    const float* u_T   = (const float*)d_in[7];
    const float* b_I   = (const float*)d_in[8];
    const float* b_T   = (const float*)d_in[9];
    const int* image_ids = (const int*)d_in[10];
    const int* text_ids  = (const int*)d_in[11];
    const int* epoch     = (const int*)d_in[12];
    const int* max_epoch = (const int*)d_in[13];
    float* out = (float*)d_out;

    gemm_fused<<<dim3(BSZ / 128, BSZ / 128), 256>>>(imf, txf, tau_I, tau_T,
                                                    image_ids, text_ids);
    copy_state<<<dim3((NST / 4 + 255) / 256, 8), 256>>>(
        s_I, s_T, u_I, u_T, b_I, b_T, tau_I, tau_T, out);
    row_merge<<<BSZ / 8, 256>>>(tau_I, s_I, u_I, b_I, image_ids, epoch, max_epoch, out);
    col_merge<<<BSZ / 8, 256>>>(tau_T, s_T, u_T, b_T, text_ids, epoch, max_epoch, out);
    finalize_kernel<<<1, 256>>>(tau_I, tau_T, image_ids, text_ids, out);
}